// round 16
// baseline (speedup 1.0000x reference)
#include <cuda_runtime.h>

#define NB 256
#define NT 1024
#define NL 64
#define TOTAL_CTAS 130

__device__ float g_norm[NB];
__device__ float g_gold2[2][NB];
__device__ int   g_done;     // zero-initialized; reset by the reducing CTA

__device__ __forceinline__ float warp_sum(float v) {
#pragma unroll
    for (int k = 16; k; k >>= 1) v += __shfl_xor_sync(0xffffffffu, v, k);
    return v;
}

// One scan step. Lane owns ONE output state o; two warps (same named barrier bid)
// cover the 64 states of one (chain, direction). Reads full u(prev) from grp[RD],
// writes u(new)[o] to grp[RD^1]. bar.sync bid,64 drains STS and orders the exchange.
#define CRF_STEP(RD, eraw, RESC) do {                                                  \
    const float ee_ = __expf(eraw);                                                    \
    const float* rbuf_ = grp[(RD)];                                                    \
    float r_ = 1.0f;                                                                   \
    if (RESC) {                                                                        \
        const float u0_ = rbuf_[0];                                                    \
        asm("rcp.approx.f32 %0, %1;" : "=f"(r_) : "f"(u0_));                           \
        Mac += (double)__logf(u0_);                                                    \
    }                                                                                  \
    unsigned long long a0_ = 0ull, a1_ = 0ull, a2_ = 0ull, a3_ = 0ull;                 \
    const ulonglong2* rp_ = (const ulonglong2*)rbuf_;                                  \
    _Pragma("unroll")                                                                  \
    for (int j_ = 0; j_ < 16; j_++) {                                                  \
        const ulonglong2 v_ = rp_[j_];                                                 \
        if (j_ & 1) {                                                                  \
            asm("fma.rn.f32x2 %0, %1, %2, %0;" : "+l"(a2_) : "l"(v_.x), "l"(Ec[2*j_]));   \
            asm("fma.rn.f32x2 %0, %1, %2, %0;" : "+l"(a3_) : "l"(v_.y), "l"(Ec[2*j_+1])); \
        } else {                                                                       \
            asm("fma.rn.f32x2 %0, %1, %2, %0;" : "+l"(a0_) : "l"(v_.x), "l"(Ec[2*j_]));   \
            asm("fma.rn.f32x2 %0, %1, %2, %0;" : "+l"(a1_) : "l"(v_.y), "l"(Ec[2*j_+1])); \
        }                                                                              \
    }                                                                                  \
    asm("add.rn.f32x2 %0, %0, %1;" : "+l"(a0_) : "l"(a1_));                            \
    asm("add.rn.f32x2 %0, %0, %1;" : "+l"(a2_) : "l"(a3_));                            \
    asm("add.rn.f32x2 %0, %0, %1;" : "+l"(a0_) : "l"(a2_));                            \
    float lo_, hi_;                                                                    \
    asm("mov.b64 {%0, %1}, %2;" : "=f"(lo_), "=f"(hi_) : "l"(a0_));                    \
    u = RESC ? ((lo_ + hi_) * ee_ * r_) : ((lo_ + hi_) * ee_);                         \
    grp[(RD) ^ 1][o] = u;                                                              \
    asm volatile("bar.sync %0, 64;" :: "r"(bid) : "memory");                           \
} while (0)

__global__ __launch_bounds__(256, 1) void crf_main_kernel(
    const float* __restrict__ scores, const int* __restrict__ targets,
    const float* __restrict__ startv, const float* __restrict__ Tmat,
    const float* __restrict__ endv, float* __restrict__ out)
{
    __shared__ __align__(16) float usm[4][2][NL];   // [group][parity][state]
    __shared__ __align__(16) float bfin[2][NL];     // beta_512 per chain
    __shared__ double bmac[2];
    __shared__ float  part[2][2];
    __shared__ int    s_last;

    const int tid = threadIdx.x;

    if (blockIdx.x >= NB / 2) {
        // ---- gold-path CTAs (blockIdx 128..129): 512 half-chains ----
        const int idx  = (blockIdx.x - NB / 2) * 256 + tid;   // 0..511
        const int b    = idx & (NB - 1);
        const int half = idx >> 8;
        const int*   tg = targets + (size_t)b * NT;
        const float* sc = scores + (size_t)b * NT * NL;
        float g; int tp, tbeg;
        if (half == 0) { tp = tg[0]; g = startv[tp] + sc[tp]; tbeg = 1; }
        else           { tp = tg[NT / 2 - 1]; g = 0.0f; tbeg = NT / 2; }
        const int tend = half ? NT : NT / 2;
#pragma unroll 8
        for (int t = tbeg; t < tend; t++) {
            const int c = tg[t];
            g += sc[(size_t)t * NL + c] + Tmat[c * NL + tp];
            tp = c;
        }
        if (half) g += endv[tp];
        g_gold2[half][b] = g;
    } else {
        // ---- forward CTAs: 2 chains x {fwd,bwd} x 2 warps; 2-warp named barriers ----
        const int w   = tid >> 5;          // warp 0..7 -> SMSP w%4 (2 warps/SMSP)
        const int l   = tid & 31;
        const int ch  = w >> 2;            // chain within CTA
        const int dir = (w >> 1) & 1;      // 0 = forward alpha, 1 = backward beta
        const int h   = w & 1;             // warp half within the group
        const int o   = h * 32 + l;        // the ONE state this lane owns
        const int bid = 1 + (w >> 1);      // named barrier id, per group
        const int b   = blockIdx.x * 2 + ch;
        float (*grp)[NL] = usm[w >> 1];

        // E for this lane: fwd needs row o of T_mat, bwd needs column o.
        unsigned long long Ec[32];
        if (dir == 0) {
#pragma unroll
            for (int j = 0; j < 32; j++) {
                const float a0 = __expf(__ldg(&Tmat[o * NL + 2 * j]));
                const float a1 = __expf(__ldg(&Tmat[o * NL + 2 * j + 1]));
                asm("mov.b64 %0, {%1, %2};" : "=l"(Ec[j]) : "f"(a0), "f"(a1));
            }
        } else {
#pragma unroll
            for (int j = 0; j < 32; j++) {
                const float a0 = __expf(__ldg(&Tmat[(2 * j) * NL + o]));
                const float a1 = __expf(__ldg(&Tmat[(2 * j + 1) * NL + o]));
                asm("mov.b64 %0, {%1, %2};" : "=l"(Ec[j]) : "f"(a0), "f"(a1));
            }
        }

        const float* sb = scores + (size_t)b * NT * NL + o;
        double Mac;
        float u;

        if (dir == 0) {
            // ============ forward: alpha_0 .. alpha_512 (512 steps) ============
            const float emit0 = sb[0];
            const float m0 = __ldg(&startv[0]) + __ldg(&scores[(size_t)b * NT * NL]);
            Mac = (double)m0;
            u = __expf(startv[o] + emit0 - m0);
            grp[0][o] = u;
            asm volatile("bar.sync %0, 64;" :: "r"(bid) : "memory");

            float e0r = sb[(size_t)1 * NL], e1r = sb[(size_t)2 * NL];
            float e2r = sb[(size_t)3 * NL], e3r = sb[(size_t)4 * NL];

#pragma unroll 1
            for (int t = 1; t <= 505; t += 4) {   // steps 1..508
                CRF_STEP(0, e0r, 1); e0r = sb[(size_t)(t + 4) * NL];
                CRF_STEP(1, e1r, 0); e1r = sb[(size_t)(t + 5) * NL];
                CRF_STEP(0, e2r, 0); e2r = sb[(size_t)(t + 6) * NL];
                CRF_STEP(1, e3r, 0); e3r = sb[(size_t)(t + 7) * NL];
            }
            CRF_STEP(0, e0r, 1);   // t = 509
            CRF_STEP(1, e1r, 0);   // t = 510
            CRF_STEP(0, e2r, 0);   // t = 511
            CRF_STEP(1, e3r, 0);   // t = 512 -> u = alpha_512[o] (scaled)
        } else {
            // ======== backward: 511 steps; emits 1022..513, last step ee=1 ========
            const float emL = sb[(size_t)(NT - 1) * NL];
            const float m0b = __ldg(&endv[0]) + __ldg(&scores[((size_t)b * NT + NT - 1) * NL]);
            Mac = (double)m0b;
            u = __expf(endv[o] + emL - m0b);
            grp[0][o] = u;
            asm volatile("bar.sync %0, 64;" :: "r"(bid) : "memory");

            float e0r = sb[(size_t)1022 * NL], e1r = sb[(size_t)1021 * NL];
            float e2r = sb[(size_t)1020 * NL], e3r = sb[(size_t)1019 * NL];

#pragma unroll 1
            for (int s = 0; s <= 504; s += 4) {   // steps 0..507
                CRF_STEP(0, e0r, 1);
                e0r = (s + 4 <= 509) ? sb[(size_t)(1022 - (s + 4)) * NL] : 0.0f;
                CRF_STEP(1, e1r, 0);
                e1r = (s + 5 <= 509) ? sb[(size_t)(1022 - (s + 5)) * NL] : 0.0f;
                CRF_STEP(0, e2r, 0);
                e2r = (s + 6 <= 509) ? sb[(size_t)(1022 - (s + 6)) * NL] : 0.0f;
                CRF_STEP(1, e3r, 0);
                e3r = (s + 7 <= 509) ? sb[(size_t)(1022 - (s + 7)) * NL] : 0.0f;
            }
            CRF_STEP(0, e0r, 1);   // s = 508
            CRF_STEP(1, e1r, 0);   // s = 509
            CRF_STEP(0, e2r, 0);   // s = 510: emit 0 -> ee = 1 -> u = beta_512[o]
        }

        // ---- combine: Z = Mac_f + Mac_b + log( sum_o alpha512[o] * beta512[o] ) ----
        if (dir == 1) {
            bfin[ch][o] = u;
            if (h == 0 && l == 0) bmac[ch] = Mac;
        }
        __syncthreads();
        if (dir == 0) {
            const float v = u * bfin[ch][o];
            const float s = warp_sum(v);
            if (l == 0) part[ch][h] = s;
        }
        __syncthreads();
        if (dir == 0 && h == 0 && l == 0)
            g_norm[b] = (float)(Mac + bmac[ch] + (double)__logf(part[ch][0] + part[ch][1]));
    }

    // ---- fused final reduction: last CTA to finish computes the mean loss ----
    __threadfence();
    __syncthreads();
    if (tid == 0) {
        const int old = atomicAdd(&g_done, 1);
        s_last = (old == TOTAL_CTAS - 1);
    }
    __syncthreads();
    if (s_last) {
        __shared__ float wred[8];
        float v = g_norm[tid] - g_gold2[0][tid] - g_gold2[1][tid];
#pragma unroll
        for (int k = 16; k; k >>= 1) v += __shfl_xor_sync(0xffffffffu, v, k);
        if ((tid & 31) == 0) wred[tid >> 5] = v;
        __syncthreads();
        if (tid == 0) {
            float s = 0.0f;
#pragma unroll
            for (int k = 0; k < 8; k++) s += wred[k];
            out[0] = s * (1.0f / (float)NB);
            g_done = 0;                      // reset for the next graph replay
        }
    }
}

extern "C" void kernel_launch(void* const* d_in, const int* in_sizes, int n_in,
                              void* d_out, int out_size)
{
    const float* scores  = (const float*)d_in[0];
    const int*   targets = (const int*)d_in[1];
    const float* startv  = (const float*)d_in[2];
    const float* Tmat    = (const float*)d_in[3];
    const float* endv    = (const float*)d_in[4];

    crf_main_kernel<<<TOTAL_CTAS, 256>>>(scores, targets, startv, Tmat, endv,
                                         (float*)d_out);
}

// round 17
// speedup vs baseline: 1.4874x; 1.4874x over previous
#include <cuda_runtime.h>

#define NB 256
#define NT 1024
#define NL 64
#define TOTAL_CTAS 132

__device__ float g_norm[NB];
__device__ float g_gold2[2][NB];
__device__ int   g_done;     // zero-initialized; reset by the reducing CTA

__device__ __forceinline__ float warp_sum(float v) {
#pragma unroll
    for (int k = 16; k; k >>= 1) v += __shfl_xor_sync(0xffffffffu, v, k);
    return v;
}

// Compiler-only memory fence: warp is converged, LSU keeps same-warp smem order;
// we only need to stop NVVM/ptxas from hoisting next step's LDS over this STS.
#define SMEM_FENCE() asm volatile("" ::: "memory")

// One scan step, intra-warp, no WARPSYNC. Reads u(prev) from buf[RD], writes
// u(new) to buf[RD^1]. Lane owns states 2l, 2l+1; E pairs in regs as f32x2.
#define CRF_STEP(RD, eraw, RESC) do {                                                  \
    const float ee0_ = __expf((eraw).x);                                               \
    const float ee1_ = __expf((eraw).y);                                               \
    const float* rbuf_ = uch[(RD)];                                                    \
    float r_ = 1.0f;                                                                   \
    if (RESC) {                                                                        \
        const float u0_ = rbuf_[0];                                                    \
        asm("rcp.approx.f32 %0, %1;" : "=f"(r_) : "f"(u0_));                           \
        Mac += (double)__logf(u0_);                                                    \
    }                                                                                  \
    unsigned long long a0_ = 0ull, a1_ = 0ull, a2_ = 0ull, a3_ = 0ull;                 \
    const ulonglong2* rp_ = (const ulonglong2*)rbuf_;                                  \
    _Pragma("unroll")                                                                  \
    for (int j_ = 0; j_ < 16; j_++) {                                                  \
        const ulonglong2 v_ = rp_[j_];                                                 \
        asm("fma.rn.f32x2 %0, %1, %2, %0;" : "+l"(a0_) : "l"(v_.x), "l"(E0[2*j_]));    \
        asm("fma.rn.f32x2 %0, %1, %2, %0;" : "+l"(a1_) : "l"(v_.y), "l"(E0[2*j_+1]));  \
        asm("fma.rn.f32x2 %0, %1, %2, %0;" : "+l"(a2_) : "l"(v_.x), "l"(E1[2*j_]));    \
        asm("fma.rn.f32x2 %0, %1, %2, %0;" : "+l"(a3_) : "l"(v_.y), "l"(E1[2*j_+1]));  \
    }                                                                                  \
    asm("add.rn.f32x2 %0, %0, %1;" : "+l"(a0_) : "l"(a1_));                            \
    asm("add.rn.f32x2 %0, %0, %1;" : "+l"(a2_) : "l"(a3_));                            \
    float x0_, y0_, x1_, y1_;                                                          \
    asm("mov.b64 {%0, %1}, %2;" : "=f"(x0_), "=f"(y0_) : "l"(a0_));                    \
    asm("mov.b64 {%0, %1}, %2;" : "=f"(x1_), "=f"(y1_) : "l"(a2_));                    \
    if (RESC) { u0r = (x0_ + y0_) * ee0_ * r_; u1r = (x1_ + y1_) * ee1_ * r_; }        \
    else      { u0r = (x0_ + y0_) * ee0_;      u1r = (x1_ + y1_) * ee1_; }             \
    unsigned long long up_;                                                            \
    asm("mov.b64 %0, {%1, %2};" : "=l"(up_) : "f"(u0r), "f"(u1r));                     \
    ((unsigned long long*)uch[(RD) ^ 1])[l] = up_;                                     \
    SMEM_FENCE();                                                                      \
} while (0)

__global__ __launch_bounds__(128, 1) void crf_main_kernel(
    const float* __restrict__ scores, const int* __restrict__ targets,
    const float* __restrict__ startv, const float* __restrict__ Tmat,
    const float* __restrict__ endv, float* __restrict__ out)
{
    __shared__ __align__(16) float usm[4][2][NL];   // [warp][parity][state]
    __shared__ __align__(16) float bfin[2][NL];     // beta_512 per chain
    __shared__ double bmac[2];
    __shared__ int    s_last;

    const int tid = threadIdx.x;

    if (blockIdx.x >= NB / 2) {
        // ---- gold-path CTAs (blockIdx 128..131): 512 half-chains ----
        const int idx  = (blockIdx.x - NB / 2) * 128 + tid;   // 0..511
        const int b    = idx & (NB - 1);
        const int half = idx >> 8;
        const int*   tg = targets + (size_t)b * NT;
        const float* sc = scores + (size_t)b * NT * NL;
        float g; int tp, tbeg;
        if (half == 0) { tp = tg[0]; g = startv[tp] + sc[tp]; tbeg = 1; }
        else           { tp = tg[NT / 2 - 1]; g = 0.0f; tbeg = NT / 2; }
        const int tend = half ? NT : NT / 2;
#pragma unroll 8
        for (int t = tbeg; t < tend; t++) {
            const int c = tg[t];
            g += sc[(size_t)t * NL + c] + Tmat[c * NL + tp];
            tp = c;
        }
        if (half) g += endv[tp];
        g_gold2[half][b] = g;
    } else {
        // ---- forward CTAs: warp = (batch, direction); depth 512 each way ----
        const int w   = tid >> 5;          // warp -> SMSP w%4, one warp each
        const int ch  = w >> 1;            // batch within CTA
        const int dir = w & 1;             // 0 = forward alpha, 1 = backward beta
        const int l   = tid & 31;
        const int b   = blockIdx.x * 2 + ch;
        const int o0  = 2 * l, o1 = 2 * l + 1;
        float (*uch)[NL] = usm[w];

        // E pairs: fwd lane needs rows o0,o1 of T_mat; bwd lane needs columns.
        unsigned long long E0[32], E1[32];
        if (dir == 0) {
#pragma unroll
            for (int j = 0; j < 32; j++) {
                const float a0 = __expf(__ldg(&Tmat[o0 * NL + 2 * j]));
                const float a1 = __expf(__ldg(&Tmat[o0 * NL + 2 * j + 1]));
                asm("mov.b64 %0, {%1, %2};" : "=l"(E0[j]) : "f"(a0), "f"(a1));
                const float c0 = __expf(__ldg(&Tmat[o1 * NL + 2 * j]));
                const float c1 = __expf(__ldg(&Tmat[o1 * NL + 2 * j + 1]));
                asm("mov.b64 %0, {%1, %2};" : "=l"(E1[j]) : "f"(c0), "f"(c1));
            }
        } else {
#pragma unroll
            for (int j = 0; j < 32; j++) {
                const float a0 = __expf(__ldg(&Tmat[(2 * j) * NL + o0]));
                const float a1 = __expf(__ldg(&Tmat[(2 * j + 1) * NL + o0]));
                asm("mov.b64 %0, {%1, %2};" : "=l"(E0[j]) : "f"(a0), "f"(a1));
                const float c0 = __expf(__ldg(&Tmat[(2 * j) * NL + o1]));
                const float c1 = __expf(__ldg(&Tmat[(2 * j + 1) * NL + o1]));
                asm("mov.b64 %0, {%1, %2};" : "=l"(E1[j]) : "f"(c0), "f"(c1));
            }
        }

        const float2* sb2 = reinterpret_cast<const float2*>(scores + (size_t)b * NT * NL) + l;
        double Mac;
        float u0r, u1r;

        if (dir == 0) {
            // ============ forward: alpha_0 .. alpha_512 (512 steps) ============
            const float2 em0 = sb2[0];
            const float p0x = startv[o0] + em0.x;
            const float p0y = startv[o1] + em0.y;
            const float m0  = __ldg(&startv[0]) + __ldg(&scores[(size_t)b * NT * NL]);
            Mac = (double)m0;
            u0r = __expf(p0x - m0);
            u1r = __expf(p0y - m0);
            {
                unsigned long long up;
                asm("mov.b64 %0, {%1, %2};" : "=l"(up) : "f"(u0r), "f"(u1r));
                ((unsigned long long*)uch[0])[l] = up;
            }
            __syncwarp();

            float2 e0p = sb2[1 * 32], e1p = sb2[2 * 32], e2p = sb2[3 * 32], e3p = sb2[4 * 32];

#pragma unroll 1
            for (int t = 1; t <= 505; t += 4) {   // steps 1..508
                CRF_STEP(0, e0p, 1); e0p = sb2[(size_t)(t + 4) * 32];
                CRF_STEP(1, e1p, 0); e1p = sb2[(size_t)(t + 5) * 32];
                CRF_STEP(0, e2p, 0); e2p = sb2[(size_t)(t + 6) * 32];
                CRF_STEP(1, e3p, 0); e3p = sb2[(size_t)(t + 7) * 32];
            }
            CRF_STEP(0, e0p, 1);   // t = 509
            CRF_STEP(1, e1p, 0);   // t = 510
            CRF_STEP(0, e2p, 0);   // t = 511
            CRF_STEP(1, e3p, 0);   // t = 512 -> alpha_512 (scaled)
        } else {
            // ======== backward: 511 steps; emits 1022..513, last step ee=1 ========
            const float2 emL = sb2[(size_t)(NT - 1) * 32];
            const float q0x = endv[o0] + emL.x;
            const float q0y = endv[o1] + emL.y;
            const float m0b = __ldg(&endv[0]) + __ldg(&scores[((size_t)b * NT + NT - 1) * NL]);
            Mac = (double)m0b;
            u0r = __expf(q0x - m0b);
            u1r = __expf(q0y - m0b);
            {
                unsigned long long up;
                asm("mov.b64 %0, {%1, %2};" : "=l"(up) : "f"(u0r), "f"(u1r));
                ((unsigned long long*)uch[0])[l] = up;
            }
            __syncwarp();

            float2 e0p = sb2[(size_t)1022 * 32], e1p = sb2[(size_t)1021 * 32];
            float2 e2p = sb2[(size_t)1020 * 32], e3p = sb2[(size_t)1019 * 32];
            const float2 zz = make_float2(0.f, 0.f);

#pragma unroll 1
            for (int s = 0; s <= 504; s += 4) {   // steps 0..507
                CRF_STEP(0, e0p, 1);
                e0p = (s + 4 <= 509) ? sb2[(size_t)(1022 - (s + 4)) * 32] : zz;
                CRF_STEP(1, e1p, 0);
                e1p = (s + 5 <= 509) ? sb2[(size_t)(1022 - (s + 5)) * 32] : zz;
                CRF_STEP(0, e2p, 0);
                e2p = (s + 6 <= 509) ? sb2[(size_t)(1022 - (s + 6)) * 32] : zz;
                CRF_STEP(1, e3p, 0);
                e3p = (s + 7 <= 509) ? sb2[(size_t)(1022 - (s + 7)) * 32] : zz;
            }
            CRF_STEP(0, e0p, 1);   // s = 508
            CRF_STEP(1, e1p, 0);   // s = 509
            CRF_STEP(0, e2p, 0);   // s = 510: ee = 1 -> beta_512
        }

        // ---- combine: Z = Mac_f + Mac_b + log( sum alpha512 ⊙ beta512 ) ----
        if (dir == 1) {
            bfin[ch][o0] = u0r;
            bfin[ch][o1] = u1r;
            if (l == 0) bmac[ch] = Mac;
        }
        __syncthreads();
        if (dir == 0) {
            const float v = u0r * bfin[ch][o0] + u1r * bfin[ch][o1];
            const float s = warp_sum(v);
            if (l == 0)
                g_norm[b] = (float)(Mac + bmac[ch] + (double)__logf(s));
        }
    }

    // ---- fused final reduction: last CTA computes the mean loss ----
    __threadfence();
    __syncthreads();
    if (tid == 0) {
        const int old = atomicAdd(&g_done, 1);
        s_last = (old == TOTAL_CTAS - 1);
    }
    __syncthreads();
    if (s_last) {
        __shared__ float wred[4];
        float v = (g_norm[tid]       - g_gold2[0][tid]       - g_gold2[1][tid])
                + (g_norm[tid + 128] - g_gold2[0][tid + 128] - g_gold2[1][tid + 128]);
#pragma unroll
        for (int k = 16; k; k >>= 1) v += __shfl_xor_sync(0xffffffffu, v, k);
        if ((tid & 31) == 0) wred[tid >> 5] = v;
        __syncthreads();
        if (tid == 0) {
            out[0] = (wred[0] + wred[1] + wred[2] + wred[3]) * (1.0f / (float)NB);
            g_done = 0;                      // reset for the next graph replay
        }
    }
}

extern "C" void kernel_launch(void* const* d_in, const int* in_sizes, int n_in,
                              void* d_out, int out_size)
{
    const float* scores  = (const float*)d_in[0];
    const int*   targets = (const int*)d_in[1];
    const float* startv  = (const float*)d_in[2];
    const float* Tmat    = (const float*)d_in[3];
    const float* endv    = (const float*)d_in[4];

    crf_main_kernel<<<TOTAL_CTAS, 128>>>(scores, targets, startv, Tmat, endv,
                                         (float*)d_out);
}